// round 4
// baseline (speedup 1.0000x reference)
#include <cuda_runtime.h>

#define BB   32
#define HW_  1600
#define A_   5
#define NGT  128
#define CC   80
#define TPB  160          // threads per block
#define PPT  2            // pred boxes per thread
#define PPB  (TPB * PPT)  // 320 preds per block; 25 blocks per batch

constexpr int NPRED       = BB * HW_ * A_;            // 256000
constexpr int IOUS_OFF    = NPRED * 4;
constexpr int CLASSES_OFF = IOUS_OFF + NPRED;
constexpr int BOXM_OFF    = CLASSES_OFF + NPRED * CC;
constexpr int IOUM_OFF    = BOXM_OFF + NPRED;
constexpr int CLSM_OFF    = IOUM_OFF + NPRED;

// ---------------------------------------------------------------------------
// Fused kernel, 2 preds/thread for ILP + LDS amortization in the pair loop.
// Blocks batch-aligned (320 preds/block, 25 blocks/batch).
// ---------------------------------------------------------------------------
__global__ void __launch_bounds__(TPB) yolo_fused_kernel(
    const float4* __restrict__ bbox_pred,   // NPRED float4
    const float*  __restrict__ iou_pred,    // NPRED
    const float*  __restrict__ gt,          // BB * NGT * 5
    const float*  __restrict__ anchors,     // 5*2
    const int*    __restrict__ num_boxes,   // BB
    float*        __restrict__ out)
{
    __shared__ float4 g4[NGT];     // x1, y1, x2+1, y2+1
    __shared__ float  sg[NGT];     // 0.375 * garea
    __shared__ float  sga[NGT];    // garea
    __shared__ float4 stbox[NGT];  // target tbox per gt
    __shared__ int    swin[PPB];   // winning gt index per local pred slot

    const int tid = threadIdx.x;
    const int t0  = blockIdx.x * PPB;
    const int b   = blockIdx.x / 25;

    swin[tid]       = -1;
    swin[tid + TPB] = -1;

    // ---- phase A: gt metadata (tid < 128) ----
    int  my_flat = 0, my_local = -1, my_cls = 0;
    bool my_valid = false;
    if (tid < NGT) {
        const float* p = gt + ((long)b * NGT + tid) * 5;
        const float gx1 = p[0], gy1 = p[1], gx2 = p[2], gy2 = p[3];
        my_cls = (int)p[4];
        g4[tid] = make_float4(gx1, gy1, gx2 + 1.0f, gy2 + 1.0f);
        const float ga = (gx2 - gx1 + 1.0f) * (gy2 - gy1 + 1.0f);
        sga[tid] = ga;
        sg[tid]  = 0.375f * ga;

        const float cx = (gx1 + gx2) * 0.5f / 32.0f;
        const float cy = (gy1 + gy2) * 0.5f / 32.0f;
        const float fcx = floorf(cx), fcy = floorf(cy);
        const int cell = (int)(fcy * 40.0f + fcx);
        const int nb = num_boxes[b];
        my_valid = (tid < nb) && (cell >= 0) && (cell < HW_);

        // anchor argmax (first max wins)
        const float gw = (gx2 / 32.0f - gx1 / 32.0f) + 1.0f;
        const float gh = (gy2 / 32.0f - gy1 / 32.0f) + 1.0f;
        const float gwh = gw * gh;
        int a_ind = 0;
        float bestA = -1.0f;
        #pragma unroll
        for (int a = 0; a < A_; a++) {
            const float aw = anchors[2 * a], ah = anchors[2 * a + 1];
            const float inta = fminf(aw, gw) * fminf(ah, gh);
            const float aiou = inta / (aw * ah + gwh - inta);
            if (aiou > bestA) { bestA = aiou; a_ind = a; }
        }

        my_flat  = (b * HW_ + cell) * A_ + a_ind;
        my_local = my_flat - t0;
        const float tw = (gx2 - gx1 + 1.0f) / 32.0f;
        const float th = (gy2 - gy1 + 1.0f) / 32.0f;
        stbox[tid] = make_float4(cx - fcx, cy - fcy,
                                 tw / anchors[2 * a_ind],
                                 th / anchors[2 * a_ind + 1]);
    }
    __syncthreads();

    // ---- phase B: scatter ownership (last index wins -> max n) ----
    if (tid < NGT && my_valid && my_local >= 0 && my_local < PPB)
        atomicMax(&swin[my_local], tid);
    __syncthreads();

    // ---- phase C: per-pred geometry (2 preds per thread) ----
    float px1[PPT], py1[PPT], px2[PPT], py2[PPT], psb[PPT], pacc[PPT], pip[PPT];
    #pragma unroll
    for (int k = 0; k < PPT; k++) {
        const int t = t0 + tid + k * TPB;
        const int hw = (t / A_) % HW_;
        const int a  = t % A_;                   // same for both k (160 % 5 == 0)
        const float4 bp = bbox_pred[t];
        pip[k] = iou_pred[t];
        const float col = (float)(hw % 40);
        const float row = (float)(hw / 40);
        const float cxp = (bp.x + col) * (1.0f / 40.0f);
        const float cyp = (bp.y + row) * (1.0f / 40.0f);
        const float bw  = bp.z * anchors[2 * a]     * (1.0f / 40.0f) * 0.5f;
        const float bh  = bp.w * anchors[2 * a + 1] * (1.0f / 40.0f) * 0.5f;
        px1[k] = (cxp - bw) * 1280.0f;
        py1[k] = (cyp - bh) * 1280.0f;
        px2[k] = (cxp + bw) * 1280.0f + 1.0f;
        py2[k] = (cyp + bh) * 1280.0f + 1.0f;
        psb[k] = 0.375f * (px2[k] - px1[k]) * (py2[k] - py1[k]);
        pacc[k] = -1e30f;
    }

    // ---- pair loop: max over ALL 128 gts of (iw*ih - 0.375*garea) ----
    // iw clamped >= 0 so ih<0 => product <= 0 < sb (no false positive).
    #pragma unroll 8
    for (int n = 0; n < NGT; n++) {
        const float4 g  = g4[n];
        const float sgn = sg[n];
        #pragma unroll
        for (int k = 0; k < PPT; k++) {
            const float iw = fmaxf(fminf(px2[k], g.z) - fmaxf(px1[k], g.x), 0.0f);
            const float ih = fminf(py2[k], g.w) - fmaxf(py1[k], g.y);
            pacc[k] = fmaxf(pacc[k], fmaf(iw, ih, -sgn));
        }
    }

    // ---- writes ----
    float4* out4 = (float4*)out;
    const int lane = tid & 31;
    #pragma unroll
    for (int k = 0; k < PPT; k++) {
        const int t = t0 + tid + k * TPB;
        const int win = swin[tid + k * TPB];
        if (win >= 0) {
            const float4 g = g4[win];
            const float iw = fmaxf(fminf(px2[k], g.z) - fmaxf(px1[k], g.x), 0.0f);
            const float ih = fmaxf(fminf(py2[k], g.w) - fmaxf(py1[k], g.y), 0.0f);
            const float inter = iw * ih;
            const float ba = (px2[k] - px1[k]) * (py2[k] - py1[k]);
            const float iou = inter / (ba + sga[win] - inter);
            out4[t] = stbox[win];
            out[IOUS_OFF + t] = iou;
            out[BOXM_OFF + t] = 1.0f;
            out[IOUM_OFF + t] = 5.0f * (1.0f - pip[k]);
            out[CLSM_OFF + t] = 1.0f;
        } else {
            out4[t] = make_float4(0.5f, 0.5f, 1.0f, 1.0f);
            out[IOUS_OFF + t] = 0.0f;
            out[BOXM_OFF + t] = 0.01f;
            out[IOUM_OFF + t] = (pacc[k] >= psb[k]) ? 0.0f : -pip[k];
            out[CLSM_OFF + t] = 0.0f;
        }

        // classes = 0, warp-coalesced for this pred's 80 floats
        const long cbase = (long)(CLASSES_OFF / 4) + (long)(t >> 5) * (32 * 20);
        const float4 z = make_float4(0.f, 0.f, 0.f, 0.f);
        #pragma unroll
        for (int i = 0; i < 20; i++)
            out4[cbase + (long)i * 32 + lane] = z;
    }

    // ---- phase D: classes 1.0-set (after this block's zero-fill) ----
    __syncthreads();
    if (tid < NGT && my_valid && my_local >= 0 && my_local < PPB)
        out[CLASSES_OFF + (long)my_flat * CC + my_cls] = 1.0f;
}

extern "C" void kernel_launch(void* const* d_in, const int* in_sizes, int n_in,
                              void* d_out, int out_size)
{
    const float4* bbox4   = (const float4*)d_in[0];
    const float*  ioup    = (const float*)d_in[1];
    const float*  gtb     = (const float*)d_in[2];
    const float*  anchors = (const float*)d_in[3];
    const int*    nboxes  = (const int*)d_in[4];
    float* out = (float*)d_out;

    yolo_fused_kernel<<<NPRED / PPB, TPB>>>(bbox4, ioup, gtb, anchors, nboxes, out);
}

// round 6
// speedup vs baseline: 1.1335x; 1.1335x over previous
#include <cuda_runtime.h>

#define BB   32
#define HW_  1600
#define A_   5
#define NGT  128
#define CC   80
#define TPB  160   // preds per block; 50 blocks per batch

constexpr int NPRED       = BB * HW_ * A_;            // 256000
constexpr int IOUS_OFF    = NPRED * 4;
constexpr int CLASSES_OFF = IOUS_OFF + NPRED;
constexpr int BOXM_OFF    = CLASSES_OFF + NPRED * CC;
constexpr int IOUM_OFF    = BOXM_OFF + NPRED;
constexpr int CLSM_OFF    = IOUM_OFF + NPRED;

// ---------------------------------------------------------------------------
// Fused kernel with warp-hull gt prefilter:
//  - warp reduces the bounding hull of its 32 pred boxes (shfl)
//  - ballot builds a 128-bit candidate mask (gt must overlap hull in x AND y;
//    skipped gts provably cannot reach the 0.6-IoU threshold for any lane)
//  - hit loop walks only set bits; arithmetic per tested pair is bit-identical
//    to the previously-passing kernel (no boundary-flip risk)
// ---------------------------------------------------------------------------
__global__ void __launch_bounds__(TPB) yolo_fused_kernel(
    const float4* __restrict__ bbox_pred,
    const float*  __restrict__ iou_pred,
    const float*  __restrict__ gt,        // BB * NGT * 5
    const float*  __restrict__ anchors,   // 5*2
    const int*    __restrict__ num_boxes, // BB
    float*        __restrict__ out)
{
    __shared__ float4 g4[NGT];     // x1, y1, x2+1, y2+1
    __shared__ float  sg[NGT];     // 0.375 * garea
    __shared__ float  sga[NGT];    // garea
    __shared__ float4 stbox[NGT];  // target tbox per gt
    __shared__ int    swin[TPB];   // winning gt index per local pred slot

    const int tid = threadIdx.x;
    const int t0  = blockIdx.x * TPB;
    const int t   = t0 + tid;
    const int b   = blockIdx.x / 50;

    swin[tid] = -1;

    // ---- phase A: gt metadata (tid < 128) ----
    int  my_flat = 0, my_local = -1, my_cls = 0;
    bool my_valid = false;
    if (tid < NGT) {
        const float* p = gt + ((long)b * NGT + tid) * 5;
        const float gx1 = p[0], gy1 = p[1], gx2 = p[2], gy2 = p[3];
        my_cls = (int)p[4];
        g4[tid] = make_float4(gx1, gy1, gx2 + 1.0f, gy2 + 1.0f);
        const float ga = (gx2 - gx1 + 1.0f) * (gy2 - gy1 + 1.0f);
        sga[tid] = ga;
        sg[tid]  = 0.375f * ga;

        const float cx = (gx1 + gx2) * 0.5f / 32.0f;
        const float cy = (gy1 + gy2) * 0.5f / 32.0f;
        const float fcx = floorf(cx), fcy = floorf(cy);
        const int cell = (int)(fcy * 40.0f + fcx);
        const int nb = num_boxes[b];
        my_valid = (tid < nb) && (cell >= 0) && (cell < HW_);

        // anchor argmax (first max wins)
        const float gw = (gx2 / 32.0f - gx1 / 32.0f) + 1.0f;
        const float gh = (gy2 / 32.0f - gy1 / 32.0f) + 1.0f;
        const float gwh = gw * gh;
        int a_ind = 0;
        float bestA = -1.0f;
        #pragma unroll
        for (int a = 0; a < A_; a++) {
            const float aw = anchors[2 * a], ah = anchors[2 * a + 1];
            const float inta = fminf(aw, gw) * fminf(ah, gh);
            const float aiou = inta / (aw * ah + gwh - inta);
            if (aiou > bestA) { bestA = aiou; a_ind = a; }
        }

        my_flat  = (b * HW_ + cell) * A_ + a_ind;
        my_local = my_flat - t0;
        const float tw = (gx2 - gx1 + 1.0f) / 32.0f;
        const float th = (gy2 - gy1 + 1.0f) / 32.0f;
        stbox[tid] = make_float4(cx - fcx, cy - fcy,
                                 tw / anchors[2 * a_ind],
                                 th / anchors[2 * a_ind + 1]);
    }
    __syncthreads();

    // ---- phase B: scatter ownership (last index wins -> max n) ----
    if (tid < NGT && my_valid && my_local >= 0 && my_local < TPB)
        atomicMax(&swin[my_local], tid);
    __syncthreads();

    // ---- phase C: pred geometry ----
    const int hw = (t / A_) % HW_;
    const int a  = t % A_;
    const float4 bp = bbox_pred[t];
    const float ip  = iou_pred[t];
    const float col = (float)(hw % 40);
    const float row = (float)(hw / 40);
    const float cxp = (bp.x + col) * (1.0f / 40.0f);
    const float cyp = (bp.y + row) * (1.0f / 40.0f);
    const float bw  = bp.z * anchors[2 * a]     * (1.0f / 40.0f) * 0.5f;
    const float bh  = bp.w * anchors[2 * a + 1] * (1.0f / 40.0f) * 0.5f;
    const float x1  = (cxp - bw) * 1280.0f;
    const float y1  = (cyp - bh) * 1280.0f;
    const float x2p = (cxp + bw) * 1280.0f + 1.0f;
    const float y2p = (cyp + bh) * 1280.0f + 1.0f;
    const float sb  = 0.375f * (x2p - x1) * (y2p - y1);

    // ---- warp hull of the 32 pred boxes ----
    float hx1 = x1, hy1 = y1, hx2 = x2p, hy2 = y2p;
    #pragma unroll
    for (int s = 16; s; s >>= 1) {
        hx1 = fminf(hx1, __shfl_xor_sync(0xffffffffu, hx1, s));
        hy1 = fminf(hy1, __shfl_xor_sync(0xffffffffu, hy1, s));
        hx2 = fmaxf(hx2, __shfl_xor_sync(0xffffffffu, hx2, s));
        hy2 = fmaxf(hy2, __shfl_xor_sync(0xffffffffu, hy2, s));
    }

    // ---- candidate masks via ballot: gt must overlap the hull in x AND y ----
    const int lane = tid & 31;
    unsigned masks[4];
    #pragma unroll
    for (int j = 0; j < 4; j++) {
        const float4 g = g4[j * 32 + lane];
        const bool cand = (fminf(hx2, g.z) > fmaxf(hx1, g.x)) &&
                          (fminf(hy2, g.w) > fmaxf(hy1, g.y));
        masks[j] = __ballot_sync(0xffffffffu, cand);
    }

    // ---- hit loop over candidates only (same arithmetic as before) ----
    float acc = -1e30f;
    #pragma unroll
    for (int j = 0; j < 4; j++) {
        unsigned m = masks[j];
        while (m) {
            const int n = j * 32 + (__ffs(m) - 1);
            m &= m - 1;
            const float4 g = g4[n];
            const float iw = fmaxf(fminf(x2p, g.z) - fmaxf(x1, g.x), 0.0f);
            const float ih = fminf(y2p, g.w) - fmaxf(y1, g.y);
            acc = fmaxf(acc, fmaf(iw, ih, -sg[n]));
        }
    }
    const bool hit = (acc >= sb);

    // ---- writes ----
    float4* out4 = (float4*)out;
    const int win = swin[tid];
    if (win >= 0) {
        const float4 g = g4[win];
        const float iw = fmaxf(fminf(x2p, g.z) - fmaxf(x1, g.x), 0.0f);
        const float ih = fmaxf(fminf(y2p, g.w) - fmaxf(y1, g.y), 0.0f);
        const float inter = iw * ih;
        const float ba = (x2p - x1) * (y2p - y1);
        const float iou = inter / (ba + sga[win] - inter);
        out4[t] = stbox[win];
        out[IOUS_OFF + t] = iou;
        out[BOXM_OFF + t] = 1.0f;
        out[IOUM_OFF + t] = 5.0f * (1.0f - ip);
        out[CLSM_OFF + t] = 1.0f;
    } else {
        out4[t] = make_float4(0.5f, 0.5f, 1.0f, 1.0f);
        out[IOUS_OFF + t] = 0.0f;
        out[BOXM_OFF + t] = 0.01f;
        out[IOUM_OFF + t] = hit ? 0.0f : -ip;
        out[CLSM_OFF + t] = 0.0f;
    }

    // classes = 0, warp-coalesced
    {
        const long cbase = (long)(CLASSES_OFF / 4) + (long)(t >> 5) * (32 * 20);
        const float4 z = make_float4(0.f, 0.f, 0.f, 0.f);
        #pragma unroll
        for (int i = 0; i < 20; i++)
            out4[cbase + (long)i * 32 + lane] = z;
    }

    // ---- phase D: classes 1.0-set ----
    __syncthreads();
    if (tid < NGT && my_valid && my_local >= 0 && my_local < TPB)
        out[CLASSES_OFF + (long)my_flat * CC + my_cls] = 1.0f;
}

extern "C" void kernel_launch(void* const* d_in, const int* in_sizes, int n_in,
                              void* d_out, int out_size)
{
    const float4* bbox4   = (const float4*)d_in[0];
    const float*  ioup    = (const float*)d_in[1];
    const float*  gtb     = (const float*)d_in[2];
    const float*  anchors = (const float*)d_in[3];
    const int*    nboxes  = (const int*)d_in[4];
    float* out = (float*)d_out;

    yolo_fused_kernel<<<NPRED / TPB, TPB>>>(bbox4, ioup, gtb, anchors, nboxes, out);
}